// round 9
// baseline (speedup 1.0000x reference)
#include <cuda_runtime.h>
#include <cstdint>
#include <math.h>

// ---------------------------------------------------------------------------
// TSI_Encoder, round 9: cg1 3xTF32 tcgen05, TS-mode A (A operand in TMEM).
//   - Warps 0-3: A producer -> mask-split -> STTM (TMEM write port, off the
//     SMEM crossbar).  Warps 4-15: B producer -> mask-split -> STS.
//   - SMEM port per chunk now carries only B (~160KB) < MMA floor -> MMA-paced.
//   - Layer1 single-pass NT=384 (dual-N MMA 256+128), layers 0/2 NT=256.
//   - cg2 cluster path from round 8 reverted (handshake was on critical path).
// ---------------------------------------------------------------------------

#define EPSF 1e-5f
#define M_TOTAL 147456   // 1024 * 144

#if defined(__CUDA_ARCH_FEAT_SM103_ALL) || defined(__CUDA_ARCH_FEAT_SM101_ALL) || \
    defined(__CUDA_ARCH_FEAT_SM100_ALL) ||                                        \
    (defined(__CUDA_ARCH_SPECIFIC__) && (__CUDA_ARCH_SPECIFIC__ >= 1000)) ||      \
    (defined(__CUDA_ARCH_FAMILY_SPECIFIC__) && (__CUDA_ARCH_FAMILY_SPECIFIC__ >= 1000))
#define HAS_TCGEN05 1
#else
#define HAS_TCGEN05 0
#endif

__device__ float g_F [147456ULL * 588];
__device__ float g_H0[147456ULL * 512];
__device__ float g_H1[147456ULL * 384];
__device__ float g_H2[147456ULL * 256];

// ======================== inline PTX helpers (103a-only) ====================
#if HAS_TCGEN05
__device__ __forceinline__ uint32_t elect_one() {
    uint32_t pred;
    asm volatile("{\n\t.reg .pred p;\n\telect.sync _|p, 0xFFFFFFFF;\n\tselp.b32 %0, 1, 0, p;\n\t}"
                 : "=r"(pred));
    return pred;
}
__device__ __forceinline__ void mbar_init(uint32_t addr, uint32_t cnt) {
    asm volatile("mbarrier.init.shared.b64 [%0], %1;" :: "r"(addr), "r"(cnt) : "memory");
}
__device__ __forceinline__ void mbar_wait(uint32_t mbar, uint32_t parity) {
    asm volatile(
        "{\n\t.reg .pred P1;\n\t"
        "WAIT_LOOP_%=:\n\t"
        "mbarrier.try_wait.parity.acquire.cta.shared::cta.b64 P1, [%0], %1, 0x989680;\n\t"
        "@P1 bra.uni WAIT_DONE_%=;\n\t"
        "bra.uni WAIT_LOOP_%=;\n\t"
        "WAIT_DONE_%=:\n\t}"
        :: "r"(mbar), "r"(parity) : "memory");
}
__device__ __forceinline__ void tmem_alloc(uint32_t dst_smem, uint32_t ncols) {
    asm volatile("tcgen05.alloc.cta_group::1.sync.aligned.shared::cta.b32 [%0], %1;"
                 :: "r"(dst_smem), "r"(ncols) : "memory");
}
__device__ __forceinline__ void tmem_relinquish() {
    asm volatile("tcgen05.relinquish_alloc_permit.cta_group::1.sync.aligned;");
}
__device__ __forceinline__ void tmem_dealloc(uint32_t tmem, uint32_t ncols) {
    asm volatile("tcgen05.dealloc.cta_group::1.sync.aligned.b32 %0, %1;" :: "r"(tmem), "r"(ncols));
}
__device__ __forceinline__ void tc_commit(uint32_t mbar) {
    asm volatile("tcgen05.commit.cta_group::1.mbarrier::arrive::one.shared::cluster.b64 [%0];"
                 :: "r"(mbar) : "memory");
}
__device__ __forceinline__ void tc_fence_after() {
    asm volatile("tcgen05.fence::after_thread_sync;" ::: "memory");
}
__device__ __forceinline__ void tc_fence_before() {
    asm volatile("tcgen05.fence::before_thread_sync;" ::: "memory");
}
__device__ __forceinline__ void tc_wait_ld() {
    asm volatile("tcgen05.wait::ld.sync.aligned;" ::: "memory");
}
__device__ __forceinline__ void tc_wait_st() {
    asm volatile("tcgen05.wait::st.sync.aligned;" ::: "memory");
}
#define LDTM_X32(r, a) \
    asm volatile( \
        "tcgen05.ld.sync.aligned.32x32b.x32.b32 " \
        "{%0, %1, %2, %3, %4, %5, %6, %7, " \
        " %8, %9, %10, %11, %12, %13, %14, %15, " \
        " %16, %17, %18, %19, %20, %21, %22, %23, " \
        " %24, %25, %26, %27, %28, %29, %30, %31}, [%32];" \
        : "=r"((r)[0]),  "=r"((r)[1]),  "=r"((r)[2]),  "=r"((r)[3]), \
          "=r"((r)[4]),  "=r"((r)[5]),  "=r"((r)[6]),  "=r"((r)[7]), \
          "=r"((r)[8]),  "=r"((r)[9]),  "=r"((r)[10]), "=r"((r)[11]), \
          "=r"((r)[12]), "=r"((r)[13]), "=r"((r)[14]), "=r"((r)[15]), \
          "=r"((r)[16]), "=r"((r)[17]), "=r"((r)[18]), "=r"((r)[19]), \
          "=r"((r)[20]), "=r"((r)[21]), "=r"((r)[22]), "=r"((r)[23]), \
          "=r"((r)[24]), "=r"((r)[25]), "=r"((r)[26]), "=r"((r)[27]), \
          "=r"((r)[28]), "=r"((r)[29]), "=r"((r)[30]), "=r"((r)[31]) \
        : "r"(a))
#define STTM_X32(a, r) \
    asm volatile( \
        "tcgen05.st.sync.aligned.32x32b.x32.b32 [%0], " \
        "{%1, %2, %3, %4, %5, %6, %7, %8, " \
        " %9, %10, %11, %12, %13, %14, %15, %16, " \
        " %17, %18, %19, %20, %21, %22, %23, %24, " \
        " %25, %26, %27, %28, %29, %30, %31, %32};" \
        :: "r"(a), \
           "r"((r)[0]),  "r"((r)[1]),  "r"((r)[2]),  "r"((r)[3]), \
           "r"((r)[4]),  "r"((r)[5]),  "r"((r)[6]),  "r"((r)[7]), \
           "r"((r)[8]),  "r"((r)[9]),  "r"((r)[10]), "r"((r)[11]), \
           "r"((r)[12]), "r"((r)[13]), "r"((r)[14]), "r"((r)[15]), \
           "r"((r)[16]), "r"((r)[17]), "r"((r)[18]), "r"((r)[19]), \
           "r"((r)[20]), "r"((r)[21]), "r"((r)[22]), "r"((r)[23]), \
           "r"((r)[24]), "r"((r)[25]), "r"((r)[26]), "r"((r)[27]), \
           "r"((r)[28]), "r"((r)[29]), "r"((r)[30]), "r"((r)[31]) \
        : "memory")

// TS-mode tf32 MMA: D[tmem] (+)= A[tmem] * B(smem desc)^T, K=8 per call.
__device__ __forceinline__ void mma_tf32_ts(uint32_t d, uint32_t a_tmem, uint64_t b_desc,
                                            uint32_t idesc, uint32_t en) {
    asm volatile(
        "{\n\t.reg .pred p;\n\t"
        "setp.ne.u32 p, %5, 0;\n\t"
        "tcgen05.mma.cta_group::1.kind::tf32 [%0], [%1], %2, %3, {%4, %4, %4, %4}, p;\n\t"
        "}"
        :: "r"(d), "r"(a_tmem), "l"(b_desc), "r"(idesc), "r"(0u), "r"(en)
        : "memory");
}
#endif  // HAS_TCGEN05

__device__ __forceinline__ uint32_t smem_u32(const void* p) {
    uint32_t a;
    asm("{ .reg .u64 t; cvta.to.shared.u64 t, %1; cvt.u32.u64 %0, t; }" : "=r"(a) : "l"(p));
    return a;
}
__device__ __forceinline__ uint32_t sw128(uint32_t off) {
    return off ^ ((off >> 3) & 0x70);
}

// SW128 K-major smem descriptor base: layout=SW128(2), version=1, SBO=64, LBO=1
static constexpr uint64_t DESC_BASE_SW128 =
    (uint64_t(2) << 61) | (uint64_t(1) << 46) | (uint64_t(64) << 32) | (uint64_t(1) << 16);
__device__ __forceinline__ uint64_t make_desc(uint32_t addr) {
    return DESC_BASE_SW128 | ((uint64_t)(addr >> 4) & 0x3FFF);
}

// idesc kind::tf32, D=F32, A=B=TF32 K-major, M=128
__device__ __forceinline__ constexpr uint32_t idesc_tf32(int n) {
    return (1u << 4) | (2u << 7) | (2u << 10) | ((uint32_t)(n / 8) << 17) | (8u << 24);
}

// Mask split: hi keeps tf32-representable top bits exactly; lo = x - hi (exact FADD).
__device__ __forceinline__ float hi_part(float x) {
    return __uint_as_float(__float_as_uint(x) & 0xFFFFE000u);
}

// ---------------------------------------------------------------------------
// Feature generation (verified; end-to-end rel_err 2.6e-7 in round 1).
// ---------------------------------------------------------------------------
__global__ __launch_bounds__(224) void featgen_kernel(const float* __restrict__ x) {
    int m = blockIdx.x;
    int b = m / 144;
    int p = m - b * 144;
    int h = p / 12;
    int w = p - h * 12;

    __shared__ float sx[168];
    int tid = threadIdx.x;
    if (tid < 168) sx[tid] = (tid == 167) ? 0.f : __ldg(&x[b * 168 + tid]);
    __syncthreads();

    if (tid < 196) {
        int i1 = tid / 14;
        int j1 = tid - i1 * 14;
        float xi = sx[i1 * 12 + h];
        float xj = sx[j1 * 12 + w];
        float d  = xj - xi;
        float r  = __frcp_rn(xi + xj + EPSF);
        float* o = &g_F[(size_t)m * 588 + tid * 3];
        o[0] = d;
        o[1] = d * r;
        o[2] = xj * r;
    }
}

// ---------------------------------------------------------------------------
// TS-mode 3xTF32 GEMM + bias + ReLU:  C[m,n0+j] = relu(sum_k A[m,k]W[n0+j,k]+b)
// 512 threads: warps 0-3 produce A (row = tid, split -> STTM to TMEM);
// warps 4-15 produce B (split -> STS). K chunks of 32, double buffered.
// TMEM cols: D [0,NT); A [384,512): buf*64 + {hi:0, lo:32} + kk*8.
// ---------------------------------------------------------------------------
template<int NT, int N, int K>
__global__ __launch_bounds__(512)
void gemm_tc_kernel(const float* __restrict__ A, const float* __restrict__ W,
                    const float* __restrict__ bias, float* __restrict__ C)
{
    extern __shared__ char smem[];
#if HAS_TCGEN05
    static_assert(NT % 32 == 0 && NT <= 384 && N % NT == 0 && K % 4 == 0, "tile assumptions");
    constexpr int BK  = 32;
    constexpr int T   = (K + BK - 1) / BK;
    constexpr int NSLOT = NT * 8;                 // B float4 slots per chunk
    constexpr int SLB   = (NSLOT + 383) / 384;    // per B-thread slots
    constexpr int BHI = 0;
    constexpr int BLO = NT * 128;
    constexpr int STAGE = 2 * NT * 128;
    constexpr int TILE0 = 1024;
    constexpr int AD    = 384;                    // TMEM col base for A buffers
    constexpr int NC0 = (NT > 256) ? 256 : NT;
    constexpr int NC1 = NT - NC0;                 // 0 or 128
    constexpr uint32_t ID0 = idesc_tf32(NC0);
    constexpr uint32_t ID1 = idesc_tf32(NC1 > 0 ? NC1 : 8);

    const uint32_t sbase = smem_u32(smem);
    const int tid = threadIdx.x;
    const int wid = tid >> 5, lid = tid & 31;
    const int m0 = blockIdx.x * 128;
    const int n0 = blockIdx.y * NT;

    if (wid == 0) {
        tmem_alloc(sbase, 512);
        tmem_relinquish();
    }
    if (tid == 0) { mbar_init(sbase + 8, 1); mbar_init(sbase + 16, 1); }
    __syncthreads();
    uint32_t tmem;
    asm volatile("ld.shared.b32 %0, [%1];" : "=r"(tmem) : "r"(sbase));

    const bool isA = (tid < 128);

    // ---- A geometry: one row per thread (tid = local row) ----
    const float* aRow = A + (size_t)(m0 + (tid & 127)) * K;
    const uint32_t a_warp = (uint32_t)(wid & 3) << 21;  // TMEM lane base for ST

    // ---- B geometry: 384 threads, SLB slots each ----
    const float* bPtr[SLB];
    uint32_t offB[SLB];
    int c4B[SLB];
    bool okB[SLB];
#pragma unroll
    for (int p = 0; p < SLB; ++p) {
        int idx = (tid - 128) + p * 384;
        bool ok = (tid >= 128) && (idx < NSLOT);
        int row = ok ? (idx >> 3) : 0;
        int c4  = (idx & 7) * 4;
        bPtr[p] = &W[(size_t)(n0 + row) * K + c4];
        offB[p] = sw128(row * 128 + c4 * 4);
        c4B[p]  = c4;
        okB[p]  = ok;
    }

    // ---- prefetch chunk 0 ----
    float4 pa[8];
    float4 pb[SLB];
    if (isA) {
#pragma unroll
        for (int i = 0; i < 8; ++i)
            pa[i] = (i * 4 < K) ? *reinterpret_cast<const float4*>(aRow + i * 4)
                                : make_float4(0.f, 0.f, 0.f, 0.f);
    } else {
#pragma unroll
        for (int p = 0; p < SLB; ++p)
            pb[p] = (okB[p] && c4B[p] < K) ? *reinterpret_cast<const float4*>(bPtr[p])
                                           : make_float4(0.f, 0.f, 0.f, 0.f);
    }

#pragma unroll 1
    for (int t = 0; t < T; ++t) {
        // prefetch next chunk
        float4 na[8], nb[SLB];
        if (t + 1 < T) {
            const int k1 = (t + 1) * BK;
            if (isA) {
#pragma unroll
                for (int i = 0; i < 8; ++i)
                    na[i] = (k1 + i * 4 < K)
                        ? *reinterpret_cast<const float4*>(aRow + k1 + i * 4)
                        : make_float4(0.f, 0.f, 0.f, 0.f);
            } else {
#pragma unroll
                for (int p = 0; p < SLB; ++p)
                    nb[p] = (okB[p] && k1 + c4B[p] < K)
                        ? *reinterpret_cast<const float4*>(bPtr[p] + k1)
                        : make_float4(0.f, 0.f, 0.f, 0.f);
            }
        }

        const int buf = t & 1;
        if (t >= 2) mbar_wait(sbase + 8 + 8 * buf, ((t - 2) >> 1) & 1);

        if (isA) {
            // ---- A: split -> STTM (hi then lo; lo recomputed to cap regs) ----
            uint32_t v[32];
#pragma unroll
            for (int i = 0; i < 8; ++i) {
                v[i * 4 + 0] = __float_as_uint(hi_part(pa[i].x));
                v[i * 4 + 1] = __float_as_uint(hi_part(pa[i].y));
                v[i * 4 + 2] = __float_as_uint(hi_part(pa[i].z));
                v[i * 4 + 3] = __float_as_uint(hi_part(pa[i].w));
            }
            STTM_X32(tmem + AD + buf * 64 + a_warp, v);
#pragma unroll
            for (int i = 0; i < 8; ++i) {
                v[i * 4 + 0] = __float_as_uint(pa[i].x - hi_part(pa[i].x));
                v[i * 4 + 1] = __float_as_uint(pa[i].y - hi_part(pa[i].y));
                v[i * 4 + 2] = __float_as_uint(pa[i].z - hi_part(pa[i].z));
                v[i * 4 + 3] = __float_as_uint(pa[i].w - hi_part(pa[i].w));
            }
            STTM_X32(tmem + AD + buf * 64 + 32 + a_warp, v);
            tc_wait_st();
        } else {
            // ---- B: split -> STS hi/lo ----
            char* stage = smem + TILE0 + buf * STAGE;
#pragma unroll
            for (int p = 0; p < SLB; ++p) {
                if (okB[p]) {
                    float4 h, l;
                    h.x = hi_part(pb[p].x); l.x = pb[p].x - h.x;
                    h.y = hi_part(pb[p].y); l.y = pb[p].y - h.y;
                    h.z = hi_part(pb[p].z); l.z = pb[p].z - h.z;
                    h.w = hi_part(pb[p].w); l.w = pb[p].w - h.w;
                    *reinterpret_cast<float4*>(stage + BHI + offB[p]) = h;
                    *reinterpret_cast<float4*>(stage + BLO + offB[p]) = l;
                }
            }
            asm volatile("fence.proxy.async.shared::cta;" ::: "memory");
        }
        __syncthreads();

        if (wid == 0 && elect_one()) {
            const uint32_t base = sbase + TILE0 + buf * STAGE;
            uint64_t dBhi = make_desc(base + BHI);
            uint64_t dBlo = make_desc(base + BLO);
            const uint32_t aHi = tmem + AD + buf * 64;
            const uint32_t aLo = aHi + 32;
#pragma unroll
            for (int kk = 0; kk < 4; ++kk) {
                uint32_t en0 = (t > 0 || kk > 0) ? 1u : 0u;
                mma_tf32_ts(tmem, aHi + kk * 8, dBhi + kk * 2, ID0, en0);
                mma_tf32_ts(tmem, aHi + kk * 8, dBlo + kk * 2, ID0, 1u);
                mma_tf32_ts(tmem, aLo + kk * 8, dBhi + kk * 2, ID0, 1u);
                if (NC1 > 0) {
                    mma_tf32_ts(tmem + NC0, aHi + kk * 8, dBhi + 2048 + kk * 2, ID1, en0);
                    mma_tf32_ts(tmem + NC0, aHi + kk * 8, dBlo + 2048 + kk * 2, ID1, 1u);
                    mma_tf32_ts(tmem + NC0, aLo + kk * 8, dBhi + 2048 + kk * 2, ID1, 1u);
                }
            }
            tc_commit(sbase + 8 + 8 * buf);
        }

        if (isA) {
#pragma unroll
            for (int i = 0; i < 8; ++i) pa[i] = na[i];
        } else {
#pragma unroll
            for (int p = 0; p < SLB; ++p) pb[p] = nb[p];
        }
    }

    // last commit covers all prior MMAs (tensor pipe in-order)
    mbar_wait(sbase + 8 + 8 * ((T - 1) & 1), ((T - 1) >> 1) & 1);
    tc_fence_after();

    // epilogue: warps 0-7; warp w = subpartition w&3, col half w>>2
    if (wid < 8) {
        const int m = m0 + (wid & 3) * 32 + lid;
        const int ch0 = (wid >> 2) * (NT / 2);
        float* crow = &C[(size_t)m * N + n0];
#pragma unroll
        for (int c0 = ch0; c0 < ch0 + NT / 2; c0 += 32) {
            uint32_t r[32];
            LDTM_X32(r, tmem + c0);
            tc_wait_ld();
#pragma unroll
            for (int j = 0; j < 32; j += 4) {
                float4 v;
                v.x = fmaxf(__uint_as_float(r[j + 0]) + __ldg(&bias[n0 + c0 + j + 0]), 0.f);
                v.y = fmaxf(__uint_as_float(r[j + 1]) + __ldg(&bias[n0 + c0 + j + 1]), 0.f);
                v.z = fmaxf(__uint_as_float(r[j + 2]) + __ldg(&bias[n0 + c0 + j + 2]), 0.f);
                v.w = fmaxf(__uint_as_float(r[j + 3]) + __ldg(&bias[n0 + c0 + j + 3]), 0.f);
                *reinterpret_cast<float4*>(crow + c0 + j) = v;
            }
        }
        tc_fence_before();
    }
    __syncthreads();
    if (wid == 0) tmem_dealloc(tmem, 512);

#else  // ---------------- SIMT fp32 fallback (plain sm_103 cubin) ----------
    float (*As)[130] = reinterpret_cast<float (*)[130]>(smem);               // [16][130]
    float (*Bs)[66]  = reinterpret_cast<float (*)[66]>(smem + 16 * 130 * 4); // [16][66]

    const int tid = threadIdx.x;
    const int m0 = blockIdx.x * 128;
    const int nbase = blockIdx.y * NT;
    const int tx = tid & 15;
    const int ty = (tid & 255) >> 4;
    const int ntiles = (K + 15) / 16;

    for (int n0 = nbase; n0 < nbase + NT; n0 += 64) {
        float acc[8][4];
#pragma unroll
        for (int i = 0; i < 8; ++i)
#pragma unroll
            for (int j = 0; j < 4; ++j) acc[i][j] = 0.f;

        for (int t = 0; t < ntiles; ++t) {
            int k0 = t * 16;
            {   // A tile: 512 float4 slots, one per thread
                int idx = tid;
                int ml  = idx >> 2;
                int kl  = (idx & 3) * 4;
                int gk  = k0 + kl;
                float4 v = make_float4(0.f, 0.f, 0.f, 0.f);
                if (gk < K)
                    v = *reinterpret_cast<const float4*>(&A[(size_t)(m0 + ml) * K + gk]);
                As[kl + 0][ml] = v.x; As[kl + 1][ml] = v.y;
                As[kl + 2][ml] = v.z; As[kl + 3][ml] = v.w;
            }
            if (tid < 256) {  // B tile: 256 slots
                int idx = tid;
                int nl  = idx >> 2;
                int kl  = (idx & 3) * 4;
                int gk  = k0 + kl;
                float4 v = make_float4(0.f, 0.f, 0.f, 0.f);
                if (gk < K)
                    v = *reinterpret_cast<const float4*>(&W[(size_t)(n0 + nl) * K + gk]);
                Bs[kl + 0][nl] = v.x; Bs[kl + 1][nl] = v.y;
                Bs[kl + 2][nl] = v.z; Bs[kl + 3][nl] = v.w;
            }
            __syncthreads();
            if (tid < 256) {
#pragma unroll
                for (int kk = 0; kk < 16; ++kk) {
                    float a[8], bb[4];
#pragma unroll
                    for (int i = 0; i < 8; ++i) a[i] = As[kk][ty * 8 + i];
#pragma unroll
                    for (int j = 0; j < 4; ++j) bb[j] = Bs[kk][tx * 4 + j];
#pragma unroll
                    for (int i = 0; i < 8; ++i)
#pragma unroll
                        for (int j = 0; j < 4; ++j)
                            acc[i][j] = fmaf(a[i], bb[j], acc[i][j]);
                }
            }
            __syncthreads();
        }

        if (tid < 256) {
#pragma unroll
            for (int i = 0; i < 8; ++i) {
                int m = m0 + ty * 8 + i;
                int n = n0 + tx * 4;
                float4 v;
                v.x = fmaxf(acc[i][0] + bias[n + 0], 0.f);
                v.y = fmaxf(acc[i][1] + bias[n + 1], 0.f);
                v.z = fmaxf(acc[i][2] + bias[n + 2], 0.f);
                v.w = fmaxf(acc[i][3] + bias[n + 3], 0.f);
                *reinterpret_cast<float4*>(&C[(size_t)m * N + n]) = v;
            }
        }
        __syncthreads();
    }
#endif
}

// ---------------------------------------------------------------------------
// Final reduction (unchanged).
// ---------------------------------------------------------------------------
__global__ __launch_bounds__(256) void reduce_kernel(
    const float* __restrict__ wm_in, float* __restrict__ out)
{
    __shared__ float wms[16 * 144];
    __shared__ float rsum[16];
    int b = blockIdx.x;
    int tid = threadIdx.x;

    for (int i = tid; i < 16 * 144; i += 256)
        wms[i] = expf(wm_in[i]);
    __syncthreads();
    if (tid < 16) {
        float s = 0.f;
        for (int p = 0; p < 144; ++p) s += wms[tid * 144 + p];
        rsum[tid] = 1.f / s;
    }
    __syncthreads();

    int g = tid >> 4;
    const float* h2 = g_H2 + (size_t)b * 144 * 256;
    float acc = 0.f;
    for (int p = 0; p < 144; ++p)
        acc = fmaf(h2[p * 256 + tid], wms[g * 144 + p], acc);
    acc *= rsum[g];
    out[b * 256 + tid] = fmaxf(acc, 0.f);
}

// ---------------------------------------------------------------------------
extern "C" void kernel_launch(void* const* d_in, const int* in_sizes, int n_in,
                              void* d_out, int out_size)
{
    const float* x  = (const float*)d_in[0];
    const float* w0 = (const float*)d_in[1];
    const float* b0 = (const float*)d_in[2];
    const float* w1 = (const float*)d_in[3];
    const float* b1 = (const float*)d_in[4];
    const float* w2 = (const float*)d_in[5];
    const float* b2 = (const float*)d_in[6];
    const float* wm = (const float*)d_in[7];
    float* out = (float*)d_out;

    float *F, *H0, *H1, *H2;
    cudaGetSymbolAddress((void**)&F,  g_F);
    cudaGetSymbolAddress((void**)&H0, g_H0);
    cudaGetSymbolAddress((void**)&H1, g_H1);
    cudaGetSymbolAddress((void**)&H2, g_H2);

    // SMEM: ctrl 1024 + 2 stages * 2*NT*128 (B hi/lo only; A lives in TMEM)
    constexpr int S0 = 1024 + 2 * (2 * 256 * 128);  // 132096 (NT=256)
    constexpr int S1 = 1024 + 2 * (2 * 384 * 128);  // 197632 (NT=384)
    constexpr int S2 = 1024 + 2 * (2 * 256 * 128);  // 132096 (NT=256)
    cudaFuncSetAttribute(gemm_tc_kernel<256, 512, 588>, cudaFuncAttributeMaxDynamicSharedMemorySize, S0);
    cudaFuncSetAttribute(gemm_tc_kernel<384, 384, 512>, cudaFuncAttributeMaxDynamicSharedMemorySize, S1);
    cudaFuncSetAttribute(gemm_tc_kernel<256, 256, 384>, cudaFuncAttributeMaxDynamicSharedMemorySize, S2);

    featgen_kernel<<<M_TOTAL, 224>>>(x);

    gemm_tc_kernel<256, 512, 588><<<dim3(M_TOTAL / 128, 2), 512, S0>>>(F,  w0, b0, H0);
    gemm_tc_kernel<384, 384, 512><<<dim3(M_TOTAL / 128, 1), 512, S1>>>(H0, w1, b1, H1);
    gemm_tc_kernel<256, 256, 384><<<dim3(M_TOTAL / 128, 1), 512, S2>>>(H1, w2, b2, H2);

    reduce_kernel<<<1024, 256>>>(wm, out);
}

// round 10
// speedup vs baseline: 1.4590x; 1.4590x over previous
#include <cuda_runtime.h>
#include <cstdint>
#include <math.h>

// ---------------------------------------------------------------------------
// TSI_Encoder, round 10: R7 skeleton (cg1 SS-mode 3xTF32, reg-prefetch,
// mask-split) widened to 512 threads: per-thread producer work halves,
// 16 warps hide LDG latency + barrier shadows, epilogue on 8 warps.
// (cg2 R8 and TS-mode R9 both measured slower and are reverted.)
// ---------------------------------------------------------------------------

#define EPSF 1e-5f
#define M_TOTAL 147456   // 1024 * 144

#if defined(__CUDA_ARCH_FEAT_SM103_ALL) || defined(__CUDA_ARCH_FEAT_SM101_ALL) || \
    defined(__CUDA_ARCH_FEAT_SM100_ALL) ||                                        \
    (defined(__CUDA_ARCH_SPECIFIC__) && (__CUDA_ARCH_SPECIFIC__ >= 1000)) ||      \
    (defined(__CUDA_ARCH_FAMILY_SPECIFIC__) && (__CUDA_ARCH_FAMILY_SPECIFIC__ >= 1000))
#define HAS_TCGEN05 1
#else
#define HAS_TCGEN05 0
#endif

__device__ float g_F [147456ULL * 588];
__device__ float g_H0[147456ULL * 512];
__device__ float g_H1[147456ULL * 384];
__device__ float g_H2[147456ULL * 256];

// ======================== inline PTX helpers (103a-only) ====================
#if HAS_TCGEN05
__device__ __forceinline__ uint32_t elect_one() {
    uint32_t pred;
    asm volatile("{\n\t.reg .pred p;\n\telect.sync _|p, 0xFFFFFFFF;\n\tselp.b32 %0, 1, 0, p;\n\t}"
                 : "=r"(pred));
    return pred;
}
__device__ __forceinline__ void mbar_init(uint32_t addr, uint32_t cnt) {
    asm volatile("mbarrier.init.shared.b64 [%0], %1;" :: "r"(addr), "r"(cnt) : "memory");
}
__device__ __forceinline__ void mbar_wait(uint32_t mbar, uint32_t parity) {
    asm volatile(
        "{\n\t.reg .pred P1;\n\t"
        "WAIT_LOOP_%=:\n\t"
        "mbarrier.try_wait.parity.acquire.cta.shared::cta.b64 P1, [%0], %1, 0x989680;\n\t"
        "@P1 bra.uni WAIT_DONE_%=;\n\t"
        "bra.uni WAIT_LOOP_%=;\n\t"
        "WAIT_DONE_%=:\n\t}"
        :: "r"(mbar), "r"(parity) : "memory");
}
__device__ __forceinline__ void tmem_alloc(uint32_t dst_smem, uint32_t ncols) {
    asm volatile("tcgen05.alloc.cta_group::1.sync.aligned.shared::cta.b32 [%0], %1;"
                 :: "r"(dst_smem), "r"(ncols) : "memory");
}
__device__ __forceinline__ void tmem_relinquish() {
    asm volatile("tcgen05.relinquish_alloc_permit.cta_group::1.sync.aligned;");
}
__device__ __forceinline__ void tmem_dealloc(uint32_t tmem, uint32_t ncols) {
    asm volatile("tcgen05.dealloc.cta_group::1.sync.aligned.b32 %0, %1;" :: "r"(tmem), "r"(ncols));
}
__device__ __forceinline__ void tc_commit(uint32_t mbar) {
    asm volatile("tcgen05.commit.cta_group::1.mbarrier::arrive::one.shared::cluster.b64 [%0];"
                 :: "r"(mbar) : "memory");
}
__device__ __forceinline__ void tc_fence_after() {
    asm volatile("tcgen05.fence::after_thread_sync;" ::: "memory");
}
__device__ __forceinline__ void tc_fence_before() {
    asm volatile("tcgen05.fence::before_thread_sync;" ::: "memory");
}
__device__ __forceinline__ void tc_wait_ld() {
    asm volatile("tcgen05.wait::ld.sync.aligned;" ::: "memory");
}
#define LDTM_X32(r, a) \
    asm volatile( \
        "tcgen05.ld.sync.aligned.32x32b.x32.b32 " \
        "{%0, %1, %2, %3, %4, %5, %6, %7, " \
        " %8, %9, %10, %11, %12, %13, %14, %15, " \
        " %16, %17, %18, %19, %20, %21, %22, %23, " \
        " %24, %25, %26, %27, %28, %29, %30, %31}, [%32];" \
        : "=r"((r)[0]),  "=r"((r)[1]),  "=r"((r)[2]),  "=r"((r)[3]), \
          "=r"((r)[4]),  "=r"((r)[5]),  "=r"((r)[6]),  "=r"((r)[7]), \
          "=r"((r)[8]),  "=r"((r)[9]),  "=r"((r)[10]), "=r"((r)[11]), \
          "=r"((r)[12]), "=r"((r)[13]), "=r"((r)[14]), "=r"((r)[15]), \
          "=r"((r)[16]), "=r"((r)[17]), "=r"((r)[18]), "=r"((r)[19]), \
          "=r"((r)[20]), "=r"((r)[21]), "=r"((r)[22]), "=r"((r)[23]), \
          "=r"((r)[24]), "=r"((r)[25]), "=r"((r)[26]), "=r"((r)[27]), \
          "=r"((r)[28]), "=r"((r)[29]), "=r"((r)[30]), "=r"((r)[31]) \
        : "r"(a))

// tf32 SS-mode MMA: D[tmem] (+)= A(smem desc) * B(smem desc)^T, K=8 per call.
__device__ __forceinline__ void mma_tf32_ss(uint32_t d, uint64_t a_desc, uint64_t b_desc,
                                            uint32_t idesc, uint32_t en) {
    asm volatile(
        "{\n\t.reg .pred p;\n\t"
        "setp.ne.u32 p, %5, 0;\n\t"
        "tcgen05.mma.cta_group::1.kind::tf32 [%0], %1, %2, %3, {%4, %4, %4, %4}, p;\n\t"
        "}"
        :: "r"(d), "l"(a_desc), "l"(b_desc), "r"(idesc), "r"(0u), "r"(en)
        : "memory");
}
#endif  // HAS_TCGEN05

__device__ __forceinline__ uint32_t smem_u32(const void* p) {
    uint32_t a;
    asm("{ .reg .u64 t; cvta.to.shared.u64 t, %1; cvt.u32.u64 %0, t; }" : "=r"(a) : "l"(p));
    return a;
}
__device__ __forceinline__ uint32_t sw128(uint32_t off) {
    return off ^ ((off >> 3) & 0x70);
}

// SW128 K-major smem descriptor base: layout=SW128(2), version=1, SBO=64, LBO=1
static constexpr uint64_t DESC_BASE_SW128 =
    (uint64_t(2) << 61) | (uint64_t(1) << 46) | (uint64_t(64) << 32) | (uint64_t(1) << 16);
__device__ __forceinline__ uint64_t make_desc(uint32_t addr) {
    return DESC_BASE_SW128 | ((uint64_t)(addr >> 4) & 0x3FFF);
}

// idesc kind::tf32, D=F32, A=B=TF32 K-major, M=128
__device__ __forceinline__ constexpr uint32_t idesc_tf32(int n) {
    return (1u << 4) | (2u << 7) | (2u << 10) | ((uint32_t)(n / 8) << 17) | (8u << 24);
}

// Mask split: hi keeps tf32-representable top bits exactly; lo = x - hi (exact FADD).
__device__ __forceinline__ void split2(float x, float& hi, float& lo) {
    hi = __uint_as_float(__float_as_uint(x) & 0xFFFFE000u);
    lo = x - hi;
}

// ---------------------------------------------------------------------------
// Feature generation (verified; end-to-end rel_err 2.6e-7 in round 1).
// ---------------------------------------------------------------------------
__global__ __launch_bounds__(224) void featgen_kernel(const float* __restrict__ x) {
    int m = blockIdx.x;
    int b = m / 144;
    int p = m - b * 144;
    int h = p / 12;
    int w = p - h * 12;

    __shared__ float sx[168];
    int tid = threadIdx.x;
    if (tid < 168) sx[tid] = (tid == 167) ? 0.f : __ldg(&x[b * 168 + tid]);
    __syncthreads();

    if (tid < 196) {
        int i1 = tid / 14;
        int j1 = tid - i1 * 14;
        float xi = sx[i1 * 12 + h];
        float xj = sx[j1 * 12 + w];
        float d  = xj - xi;
        float r  = __frcp_rn(xi + xj + EPSF);
        float* o = &g_F[(size_t)m * 588 + tid * 3];
        o[0] = d;
        o[1] = d * r;
        o[2] = xj * r;
    }
}

// ---------------------------------------------------------------------------
// GEMM + bias + ReLU:  C[m, n0+j] = relu( sum_k A[m,k] * W[n0+j,k] + bias )
// CTA tile 128 x NT; K chunks of 32; double-buffered hi/lo SMEM stages;
// 512 threads, register-prefetched LDGs; epilogue on 8 warps.
// ---------------------------------------------------------------------------
template<int NT, int N, int K>
__global__ __launch_bounds__(512)
void gemm_tc_kernel(const float* __restrict__ A, const float* __restrict__ W,
                    const float* __restrict__ bias, float* __restrict__ C)
{
    extern __shared__ char smem[];
#if HAS_TCGEN05
    static_assert(NT % 64 == 0 && NT <= 256 && N % NT == 0 && K % 4 == 0, "tile assumptions");
    constexpr int BK  = 32;
    constexpr int T   = (K + BK - 1) / BK;
    constexpr int SLB = NT * 8 / 512;            // B float4 slots per thread (4 / 3)
    constexpr int AHI = 0, ALO = 16384, BHI = 32768;
    constexpr int BLO   = BHI + NT * 128;
    constexpr int STAGE = 32768 + 2 * NT * 128;
    constexpr int TILE0 = 1024;
    constexpr uint32_t ID = idesc_tf32(NT);

    const uint32_t sbase = smem_u32(smem);
    const int tid = threadIdx.x;
    const int wid = tid >> 5, lid = tid & 31;
    const int m0 = blockIdx.x * 128;
    const int n0 = blockIdx.y * NT;

    if (wid == 0) {
        tmem_alloc(sbase, 512);
        tmem_relinquish();
    }
    if (tid == 0) { mbar_init(sbase + 8, 1); mbar_init(sbase + 16, 1); }
    __syncthreads();
    uint32_t tmem;
    asm volatile("ld.shared.b32 %0, [%1];" : "=r"(tmem) : "r"(sbase));

    // ---- per-thread slot geometry (k-invariant): pointers + smem offsets ----
    const float* aPtr[2];
    uint32_t offA[2];
    int c4A[2];
#pragma unroll
    for (int p = 0; p < 2; ++p) {
        int slot = tid + p * 512;                // 1024 A slots
        int row  = slot >> 3;
        int c4   = (slot & 7) * 4;
        aPtr[p]  = &A[(size_t)(m0 + row) * K + c4];
        offA[p]  = sw128(row * 128 + c4 * 4);
        c4A[p]   = c4;
    }
    const float* bPtr[SLB];
    uint32_t offB[SLB];
    int c4B[SLB];
#pragma unroll
    for (int p = 0; p < SLB; ++p) {
        int slot = tid + p * 512;                // NT*8 B slots
        int row  = slot >> 3;
        int c4   = (slot & 7) * 4;
        bPtr[p]  = &W[(size_t)(n0 + row) * K + c4];
        offB[p]  = sw128(row * 128 + c4 * 4);
        c4B[p]   = c4;
    }

    float4 pa[2], pb[SLB];
    // preamble: load chunk 0
#pragma unroll
    for (int p = 0; p < 2; ++p)
        pa[p] = (c4A[p] < K) ? *reinterpret_cast<const float4*>(aPtr[p])
                             : make_float4(0.f, 0.f, 0.f, 0.f);
#pragma unroll
    for (int p = 0; p < SLB; ++p)
        pb[p] = (c4B[p] < K) ? *reinterpret_cast<const float4*>(bPtr[p])
                             : make_float4(0.f, 0.f, 0.f, 0.f);

#pragma unroll 1
    for (int t = 0; t < T; ++t) {
        // ---- issue next chunk's loads first (latency hidden behind this chunk) ----
        float4 na[2], nb[SLB];
        if (t + 1 < T) {
            const int k1 = (t + 1) * BK;
#pragma unroll
            for (int p = 0; p < 2; ++p)
                na[p] = (k1 + c4A[p] < K) ? *reinterpret_cast<const float4*>(aPtr[p] + k1)
                                          : make_float4(0.f, 0.f, 0.f, 0.f);
#pragma unroll
            for (int p = 0; p < SLB; ++p)
                nb[p] = (k1 + c4B[p] < K) ? *reinterpret_cast<const float4*>(bPtr[p] + k1)
                                          : make_float4(0.f, 0.f, 0.f, 0.f);
        }

        const int buf = t & 1;
        char* stage = smem + TILE0 + buf * STAGE;
        if (t >= 2) mbar_wait(sbase + 8 + 8 * buf, ((t - 2) >> 1) & 1);

        // ---- mask-split + STS (alu/fma pipes; no cvt) ----
#pragma unroll
        for (int p = 0; p < 2; ++p) {
            float4 h, l;
            split2(pa[p].x, h.x, l.x); split2(pa[p].y, h.y, l.y);
            split2(pa[p].z, h.z, l.z); split2(pa[p].w, h.w, l.w);
            *reinterpret_cast<float4*>(stage + AHI + offA[p]) = h;
            *reinterpret_cast<float4*>(stage + ALO + offA[p]) = l;
        }
#pragma unroll
        for (int p = 0; p < SLB; ++p) {
            float4 h, l;
            split2(pb[p].x, h.x, l.x); split2(pb[p].y, h.y, l.y);
            split2(pb[p].z, h.z, l.z); split2(pb[p].w, h.w, l.w);
            *reinterpret_cast<float4*>(stage + BHI + offB[p]) = h;
            *reinterpret_cast<float4*>(stage + BLO + offB[p]) = l;
        }
        asm volatile("fence.proxy.async.shared::cta;" ::: "memory");
        __syncthreads();

        if (wid == 0 && elect_one()) {
            const uint32_t base = sbase + TILE0 + buf * STAGE;
            uint64_t dAhi = make_desc(base + AHI);
            uint64_t dAlo = make_desc(base + ALO);
            uint64_t dBhi = make_desc(base + BHI);
            uint64_t dBlo = make_desc(base + BLO);
#pragma unroll
            for (int kk = 0; kk < 4; ++kk) {
                uint32_t en0 = (t > 0 || kk > 0) ? 1u : 0u;
                mma_tf32_ss(tmem, dAhi + kk * 2, dBhi + kk * 2, ID, en0);
                mma_tf32_ss(tmem, dAhi + kk * 2, dBlo + kk * 2, ID, 1u);
                mma_tf32_ss(tmem, dAlo + kk * 2, dBhi + kk * 2, ID, 1u);
            }
            tc_commit(sbase + 8 + 8 * buf);
        }

        // rotate prefetch registers
#pragma unroll
        for (int p = 0; p < 2; ++p) pa[p] = na[p];
#pragma unroll
        for (int p = 0; p < SLB; ++p) pb[p] = nb[p];
    }

    // Wait for the last commit (tensor pipe is in-order), then read D.
    mbar_wait(sbase + 8 + 8 * ((T - 1) & 1), ((T - 1) >> 1) & 1);
    tc_fence_after();

    // epilogue: warps 0-7; warp w = subpartition w&3, col half w>>2
    if (wid < 8) {
        const int m = m0 + (wid & 3) * 32 + lid;
        const int ch0 = (wid >> 2) * (NT / 2);
        float* crow = &C[(size_t)m * N + n0];
#pragma unroll
        for (int c0 = ch0; c0 < ch0 + NT / 2; c0 += 32) {
            uint32_t r[32];
            LDTM_X32(r, tmem + c0);
            tc_wait_ld();
#pragma unroll
            for (int j = 0; j < 32; j += 4) {
                float4 v;
                v.x = fmaxf(__uint_as_float(r[j + 0]) + __ldg(&bias[n0 + c0 + j + 0]), 0.f);
                v.y = fmaxf(__uint_as_float(r[j + 1]) + __ldg(&bias[n0 + c0 + j + 1]), 0.f);
                v.z = fmaxf(__uint_as_float(r[j + 2]) + __ldg(&bias[n0 + c0 + j + 2]), 0.f);
                v.w = fmaxf(__uint_as_float(r[j + 3]) + __ldg(&bias[n0 + c0 + j + 3]), 0.f);
                *reinterpret_cast<float4*>(crow + c0 + j) = v;
            }
        }
        tc_fence_before();
    }
    __syncthreads();
    if (wid == 0) tmem_dealloc(tmem, 512);

#else  // ---------------- SIMT fp32 fallback (plain sm_103 cubin) ----------
    float (*As)[130] = reinterpret_cast<float (*)[130]>(smem);               // [16][130]
    float (*Bs)[66]  = reinterpret_cast<float (*)[66]>(smem + 16 * 130 * 4); // [16][66]

    const int tid = threadIdx.x;
    const int m0 = blockIdx.x * 128;
    const int nbase = blockIdx.y * NT;
    const int tx = tid & 15;
    const int ty = (tid & 255) >> 4;
    const int ntiles = (K + 15) / 16;

    for (int n0 = nbase; n0 < nbase + NT; n0 += 64) {
        float acc[8][4];
#pragma unroll
        for (int i = 0; i < 8; ++i)
#pragma unroll
            for (int j = 0; j < 4; ++j) acc[i][j] = 0.f;

        for (int t = 0; t < ntiles; ++t) {
            int k0 = t * 16;
            {   // A tile: 512 float4 slots, one per thread
                int idx = tid;
                int ml  = idx >> 2;
                int kl  = (idx & 3) * 4;
                int gk  = k0 + kl;
                float4 v = make_float4(0.f, 0.f, 0.f, 0.f);
                if (gk < K)
                    v = *reinterpret_cast<const float4*>(&A[(size_t)(m0 + ml) * K + gk]);
                As[kl + 0][ml] = v.x; As[kl + 1][ml] = v.y;
                As[kl + 2][ml] = v.z; As[kl + 3][ml] = v.w;
            }
            if (tid < 256) {  // B tile: 256 slots
                int idx = tid;
                int nl  = idx >> 2;
                int kl  = (idx & 3) * 4;
                int gk  = k0 + kl;
                float4 v = make_float4(0.f, 0.f, 0.f, 0.f);
                if (gk < K)
                    v = *reinterpret_cast<const float4*>(&W[(size_t)(n0 + nl) * K + gk]);
                Bs[kl + 0][nl] = v.x; Bs[kl + 1][nl] = v.y;
                Bs[kl + 2][nl] = v.z; Bs[kl + 3][nl] = v.w;
            }
            __syncthreads();
            if (tid < 256) {
#pragma unroll
                for (int kk = 0; kk < 16; ++kk) {
                    float a[8], bb[4];
#pragma unroll
                    for (int i = 0; i < 8; ++i) a[i] = As[kk][ty * 8 + i];
#pragma unroll
                    for (int j = 0; j < 4; ++j) bb[j] = Bs[kk][tx * 4 + j];
#pragma unroll
                    for (int i = 0; i < 8; ++i)
#pragma unroll
                        for (int j = 0; j < 4; ++j)
                            acc[i][j] = fmaf(a[i], bb[j], acc[i][j]);
                }
            }
            __syncthreads();
        }

        if (tid < 256) {
#pragma unroll
            for (int i = 0; i < 8; ++i) {
                int m = m0 + ty * 8 + i;
                int n = n0 + tx * 4;
                float4 v;
                v.x = fmaxf(acc[i][0] + bias[n + 0], 0.f);
                v.y = fmaxf(acc[i][1] + bias[n + 1], 0.f);
                v.z = fmaxf(acc[i][2] + bias[n + 2], 0.f);
                v.w = fmaxf(acc[i][3] + bias[n + 3], 0.f);
                *reinterpret_cast<float4*>(&C[(size_t)m * N + n]) = v;
            }
        }
        __syncthreads();
    }
#endif
}

// ---------------------------------------------------------------------------
// Final reduction (unchanged).
// ---------------------------------------------------------------------------
__global__ __launch_bounds__(256) void reduce_kernel(
    const float* __restrict__ wm_in, float* __restrict__ out)
{
    __shared__ float wms[16 * 144];
    __shared__ float rsum[16];
    int b = blockIdx.x;
    int tid = threadIdx.x;

    for (int i = tid; i < 16 * 144; i += 256)
        wms[i] = expf(wm_in[i]);
    __syncthreads();
    if (tid < 16) {
        float s = 0.f;
        for (int p = 0; p < 144; ++p) s += wms[tid * 144 + p];
        rsum[tid] = 1.f / s;
    }
    __syncthreads();

    int g = tid >> 4;
    const float* h2 = g_H2 + (size_t)b * 144 * 256;
    float acc = 0.f;
    for (int p = 0; p < 144; ++p)
        acc = fmaf(h2[p * 256 + tid], wms[g * 144 + p], acc);
    acc *= rsum[g];
    out[b * 256 + tid] = fmaxf(acc, 0.f);
}

// ---------------------------------------------------------------------------
extern "C" void kernel_launch(void* const* d_in, const int* in_sizes, int n_in,
                              void* d_out, int out_size)
{
    const float* x  = (const float*)d_in[0];
    const float* w0 = (const float*)d_in[1];
    const float* b0 = (const float*)d_in[2];
    const float* w1 = (const float*)d_in[3];
    const float* b1 = (const float*)d_in[4];
    const float* w2 = (const float*)d_in[5];
    const float* b2 = (const float*)d_in[6];
    const float* wm = (const float*)d_in[7];
    float* out = (float*)d_out;

    float *F, *H0, *H1, *H2;
    cudaGetSymbolAddress((void**)&F,  g_F);
    cudaGetSymbolAddress((void**)&H0, g_H0);
    cudaGetSymbolAddress((void**)&H1, g_H1);
    cudaGetSymbolAddress((void**)&H2, g_H2);

    // SMEM: ctrl 1024 + 2 stages * (32768 + 2*NT*128)
    constexpr int S0 = 1024 + 2 * (32768 + 2 * 256 * 128);  // 197632 (NT=256)
    constexpr int S1 = 1024 + 2 * (32768 + 2 * 192 * 128);  // 164864 (NT=192)
    constexpr int S2 = 1024 + 2 * (32768 + 2 * 256 * 128);  // 197632 (NT=256)
    cudaFuncSetAttribute(gemm_tc_kernel<256, 512, 588>, cudaFuncAttributeMaxDynamicSharedMemorySize, S0);
    cudaFuncSetAttribute(gemm_tc_kernel<192, 384, 512>, cudaFuncAttributeMaxDynamicSharedMemorySize, S1);
    cudaFuncSetAttribute(gemm_tc_kernel<256, 256, 384>, cudaFuncAttributeMaxDynamicSharedMemorySize, S2);

    featgen_kernel<<<M_TOTAL, 224>>>(x);

    gemm_tc_kernel<256, 512, 588><<<dim3(M_TOTAL / 128, 2), 512, S0>>>(F,  w0, b0, H0);
    gemm_tc_kernel<192, 384, 512><<<dim3(M_TOTAL / 128, 2), 512, S1>>>(H0, w1, b1, H1);
    gemm_tc_kernel<256, 256, 384><<<dim3(M_TOTAL / 128, 1), 512, S2>>>(H1, w2, b2, H2);

    reduce_kernel<<<1024, 256>>>(wm, out);
}